// round 13
// baseline (speedup 1.0000x reference)
#include <cuda_runtime.h>
#include <cstdint>
#include <cuda_fp16.h>
#include <mma.h>

using namespace nvcuda;

// Problem constants
#define BB    32
#define NWIN  64
#define LL    49
#define DD    192
#define PROJ_ 256
#define HEADS 8
#define HD    32
#define MTOT  (BB * NWIN * LL)   // 100352

#define ALDH 40      // A smem stride in halves
#define QLDH 40      // attention q/k/v stride (halves)
#define PLDH 72      // attention P stride (halves)
#define SLDF 68      // score/staging stride (floats)

// Scratch (device globals: allocation-free per harness rules)
__device__ __half g_Q[MTOT * PROJ_];
__device__ __half g_K[MTOT * PROJ_];
__device__ __half g_V[MTOT * PROJ_];
__device__ __half g_Wh[4 * DD * PROJ_];  // fp16-rounded weights (Wq|Wk|Wv|Ww)

// 0 = int32 mask, 1 = byte mask (bool/uint8), 2 = float32 mask
__device__ int g_mask_kind;

// ---------------------------------------------------------------------------
__global__ void detect_mask_kind(const unsigned int* __restrict__ m)
{
    const int lane = threadIdx.x;
    int not_int = 0, not_flt = 0;
    for (int i = lane; i < 256; i += 32) {
        unsigned int w = m[i];
        if (w > 1u) not_int = 1;
        if (w != 0u && w != 0x3F800000u) not_flt = 1;
    }
    not_int = __any_sync(0xffffffffu, not_int);
    not_flt = __any_sync(0xffffffffu, not_flt);
    if (lane == 0) {
        int kind;
        if (!not_int)      kind = 0;
        else if (!not_flt) kind = 2;
        else               kind = 1;
        g_mask_kind = kind;
    }
}

// ---------------------------------------------------------------------------
// One launch: round all 4 weight matrices to fp16 into contiguous g_Wh.
// ---------------------------------------------------------------------------
__global__ void round_all4(const float* __restrict__ s0, const float* __restrict__ s1,
                           const float* __restrict__ s2, const float* __restrict__ s3,
                           __half* __restrict__ dst, int n)
{
    const int i = blockIdx.x * 256 + threadIdx.x;
    if (i < 4 * n) {
        const int seg = i / n;
        const int off = i - seg * n;
        const float* s = (seg == 0) ? s0 : (seg == 1) ? s1 : (seg == 2) ? s2 : s3;
        dst[i] = __float2half_rn(s[off]);
    }
}

// ---------------------------------------------------------------------------
// cp.async helpers
// ---------------------------------------------------------------------------
__device__ __forceinline__ void cpa16(unsigned int saddr, const void* gptr)
{
    asm volatile("cp.async.ca.shared.global [%0], [%1], 16;\n" :: "r"(saddr), "l"(gptr));
}
__device__ __forceinline__ void cpa_commit()
{
    asm volatile("cp.async.commit_group;\n");
}
template <int N>
__device__ __forceinline__ void cpa_wait()
{
    asm volatile("cp.async.wait_group %0;\n" :: "n"(N));
}

// ---------------------------------------------------------------------------
// FP16 projection GEMM: Ch[M,N] = half(A_f32[M,K] @ Bh[K,N] + bias)
// BM=128, BN=128, BK=32, 256 threads = 8 warps (4 rows x 2 cols),
// warp tile 32x64 (fc[2][4], 64 acc regs) for 16 warps/SM.
// ---------------------------------------------------------------------------
__global__ __launch_bounds__(256, 2) void gemm_fp16_proj(
    const float* __restrict__ A, const __half* __restrict__ Bh,
    const float* __restrict__ bias, __half* __restrict__ C,
    int Nd, int Kd)
{
    constexpr int BN_ = 128;
    constexpr int BLDH = BN_ + 8;
    constexpr int ABUFH = 128 * ALDH;
    constexpr int BBUFH = 32 * BLDH;

    extern __shared__ char smraw[];
    float*  BiasR = (float*)smraw;                    // BN_ f32
    __half* As    = (__half*)(smraw + BN_ * 4);       // 2*ABUFH halves
    __half* Bs    = As + 2 * ABUFH;                   // 2*BBUFH halves
    float*  Cs    = (float*)(smraw + BN_ * 4);        // staging alias (128 x SLDF)

    const int tid = threadIdx.x;
    const int wid = tid >> 5;
    const int m0 = blockIdx.y * 128;
    const int n0 = blockIdx.x * BN_;

    const int wr = wid & 3;
    const int wc = wid >> 2;
    const int lwr = wr * 32;
    const int lwc = wc * 64;

    const unsigned int bs_base = (unsigned int)__cvta_generic_to_shared(Bs);

    for (int c = tid; c < BN_; c += 256) BiasR[c] = bias ? bias[n0 + c] : 0.0f;

    wmma::fragment<wmma::matrix_a, 16, 16, 16, __half, wmma::row_major> fa[2];
    wmma::fragment<wmma::matrix_b, 16, 16, 16, __half, wmma::row_major> fb;
    wmma::fragment<wmma::accumulator, 16, 16, 16, float> fc[2][4];

#pragma unroll
    for (int i = 0; i < 2; i++)
#pragma unroll
        for (int j = 0; j < 4; j++)
            wmma::fill_fragment(fc[i][j], 0.0f);

    const int niter = Kd / 32;

    auto load_A = [&](int buf, int k0) {
        __half* Ab = As + buf * ABUFH;
#pragma unroll
        for (int p = 0; p < 4; p++) {
            const int idx = tid + p * 256;
            const int row = idx >> 3;
            const int ch4 = (idx & 7) << 2;
            float4 v = *reinterpret_cast<const float4*>(
                &A[(size_t)(m0 + row) * Kd + k0 + ch4]);
            union { __half2 h[2]; uint2 u; } pk;
            pk.h[0] = __floats2half2_rn(v.x, v.y);
            pk.h[1] = __floats2half2_rn(v.z, v.w);
            *reinterpret_cast<uint2*>(&Ab[row * ALDH + ch4]) = pk.u;
        }
    };
    auto load_B = [&](int buf, int k0) {
        const unsigned int bsb = bs_base + (unsigned int)(buf * BBUFH) * 2u;
#pragma unroll
        for (int p = 0; p < 2; p++) {
            const int idx = tid + p * 256;
            const int row = idx >> 4;
            const int ch8 = (idx & 15) << 3;
            cpa16(bsb + (unsigned int)(row * BLDH + ch8) * 2u,
                  &Bh[(size_t)(k0 + row) * Nd + n0 + ch8]);
        }
        cpa_commit();
    };

    load_B(0, 0);
    load_A(0, 0);

    for (int it = 0; it < niter; it++) {
        const int buf = it & 1;
        if (it + 1 < niter) {
            load_B(buf ^ 1, (it + 1) * 32);
            load_A(buf ^ 1, (it + 1) * 32);
            cpa_wait<1>();
        } else {
            cpa_wait<0>();
        }
        __syncthreads();

        const __half* Ab = As + buf * ABUFH;
        const __half* Bb = Bs + buf * BBUFH;

#pragma unroll
        for (int ks = 0; ks < 32; ks += 16) {
#pragma unroll
            for (int i = 0; i < 2; i++)
                wmma::load_matrix_sync(fa[i], &Ab[(lwr + i * 16) * ALDH + ks], ALDH);
#pragma unroll
            for (int j = 0; j < 4; j++) {
                wmma::load_matrix_sync(fb, &Bb[ks * BLDH + lwc + j * 16], BLDH);
#pragma unroll
                for (int i = 0; i < 2; i++)
                    wmma::mma_sync(fc[i][j], fa[i], fb, fc[i][j]);
            }
        }
        __syncthreads();
    }

    // Epilogue: two 64-col passes. Warps with wc==jh stage their fragments
    // in f32 smem; then all threads add bias, convert to half, store.
#pragma unroll
    for (int jh = 0; jh < 2; jh++) {
        if (wc == jh) {
#pragma unroll
            for (int j = 0; j < 4; j++)
#pragma unroll
                for (int i = 0; i < 2; i++)
                    wmma::store_matrix_sync(&Cs[(lwr + i * 16) * SLDF + j * 16],
                                            fc[i][j], SLDF, wmma::mem_row_major);
        }
        __syncthreads();
        for (int idx = tid; idx < 128 * 16; idx += 256) {
            const int r  = idx >> 4;
            const int c4 = (idx & 15) << 2;
            const int cg = jh * 64 + c4;
            union { __half2 h[2]; uint2 u; } pk;
            pk.h[0] = __floats2half2_rn(Cs[r * SLDF + c4]     + BiasR[cg],
                                        Cs[r * SLDF + c4 + 1] + BiasR[cg + 1]);
            pk.h[1] = __floats2half2_rn(Cs[r * SLDF + c4 + 2] + BiasR[cg + 2],
                                        Cs[r * SLDF + c4 + 3] + BiasR[cg + 3]);
            *reinterpret_cast<uint2*>(&C[(size_t)(m0 + r) * Nd + n0 + cg]) = pk.u;
        }
        __syncthreads();
    }
}

// ---------------------------------------------------------------------------
// FP16 out GEMM: C_f32[M,N] = Ah[M,K] @ Bh[K,N] + bias  (unchanged from R12)
// BM=128, BN=64, BK=32, 128 threads (2x2 warps, tile 64x32).
// ---------------------------------------------------------------------------
__global__ __launch_bounds__(128) void gemm_fp16_out(
    const __half* __restrict__ Ah, const __half* __restrict__ Bh,
    const float* __restrict__ bias, float* __restrict__ C,
    int Nd, int Kd)
{
    constexpr int BN_ = 64;
    constexpr int BLDH = BN_ + 8;
    constexpr int FJ   = 2;
    constexpr int ABUFH = 128 * ALDH;
    constexpr int BBUFH = 32 * BLDH;

    extern __shared__ char smraw[];
    float*  BiasT = (float*)smraw;                 // 16 x (BN_+4) f32
    __half* As    = (__half*)(smraw + 16 * (BN_ + 4) * 4);
    __half* Bs    = As + 2 * ABUFH;

    const int tid = threadIdx.x;
    const int wid = tid >> 5;
    const int m0 = blockIdx.y * 128;
    const int n0 = blockIdx.x * BN_;

    const int lwr = (wid >> 1) * 64;
    const int lwc = (wid & 1) * 32;

    const int aro = tid >> 2;
    const int ac8 = (tid & 3) << 3;
    const int br  = tid >> 3;
    const int bc8 = (tid & 7) << 3;

    const unsigned int as_base = (unsigned int)__cvta_generic_to_shared(As);
    const unsigned int bs_base = (unsigned int)__cvta_generic_to_shared(Bs);

    for (int idx = tid; idx < 16 * BN_; idx += 128) {
        const int r = idx / BN_;
        const int c = idx - r * BN_;
        BiasT[r * (BN_ + 4) + c] = bias ? bias[n0 + c] : 0.0f;
    }

    wmma::fragment<wmma::matrix_a, 16, 16, 16, __half, wmma::row_major> fa[4];
    wmma::fragment<wmma::matrix_b, 16, 16, 16, __half, wmma::row_major> fb;
    wmma::fragment<wmma::accumulator, 16, 16, 16, float> fc[4][FJ];

#pragma unroll
    for (int i = 0; i < 4; i++)
#pragma unroll
        for (int j = 0; j < FJ; j++)
            wmma::fill_fragment(fc[i][j], 0.0f);

    const int niter = Kd / 32;

    auto load_stage = [&](int buf, int k0) {
        const unsigned int asb = as_base + (unsigned int)(buf * ABUFH) * 2u;
        const unsigned int bsb = bs_base + (unsigned int)(buf * BBUFH) * 2u;
#pragma unroll
        for (int p = 0; p < 4; p++) {
            const int row = aro + p * 32;
            cpa16(asb + (unsigned int)(row * ALDH + ac8) * 2u,
                  &Ah[(size_t)(m0 + row) * Kd + k0 + ac8]);
        }
#pragma unroll
        for (int p = 0; p < 2; p++) {
            const int row = br + p * 16;
            cpa16(bsb + (unsigned int)(row * BLDH + bc8) * 2u,
                  &Bh[(size_t)(k0 + row) * Nd + n0 + bc8]);
        }
        cpa_commit();
    };

    load_stage(0, 0);

    for (int it = 0; it < niter; it++) {
        const int buf = it & 1;
        if (it + 1 < niter) {
            load_stage(buf ^ 1, (it + 1) * 32);
            cpa_wait<1>();
        } else {
            cpa_wait<0>();
        }
        __syncthreads();

        const __half* Ab = As + buf * ABUFH;
        const __half* Bb = Bs + buf * BBUFH;

#pragma unroll
        for (int ks = 0; ks < 32; ks += 16) {
#pragma unroll
            for (int i = 0; i < 4; i++)
                wmma::load_matrix_sync(fa[i], &Ab[(lwr + i * 16) * ALDH + ks], ALDH);
#pragma unroll
            for (int j = 0; j < FJ; j++) {
                wmma::load_matrix_sync(fb, &Bb[ks * BLDH + lwc + j * 16], BLDH);
#pragma unroll
                for (int i = 0; i < 4; i++)
                    wmma::mma_sync(fc[i][j], fa[i], fb, fc[i][j]);
            }
        }
        __syncthreads();
    }

    wmma::fragment<wmma::accumulator, 16, 16, 16, float> fbias;
#pragma unroll
    for (int j = 0; j < FJ; j++) {
        wmma::load_matrix_sync(fbias, &BiasT[lwc + j * 16], BN_ + 4, wmma::mem_row_major);
#pragma unroll
        for (int i = 0; i < 4; i++) {
#pragma unroll
            for (int t = 0; t < fbias.num_elements; t++)
                fc[i][j].x[t] += fbias.x[t];
            wmma::store_matrix_sync(
                &C[(size_t)(m0 + lwr + i * 16) * Nd + n0 + lwc + j * 16],
                fc[i][j], Nd, wmma::mem_row_major);
        }
    }
}

// ---------------------------------------------------------------------------
// FP16 window attention, 128 threads (4 warps) per head: double per-warp MMA
// ILP, cheaper barriers, 5 CTAs/SM.
// ---------------------------------------------------------------------------
__global__ __launch_bounds__(128) void attn_fp16(
    const __half* __restrict__ Q, const __half* __restrict__ K,
    const __half* __restrict__ V, const void* __restrict__ mask,
    __half* __restrict__ O)
{
    __shared__ __align__(16) __half qs[64 * QLDH];
    __shared__ __align__(16) __half ks_[64 * QLDH];
    __shared__ __align__(16) __half vs[64 * QLDH];
    __shared__ __align__(16) __half ph[64 * PLDH];
    __shared__ __align__(16) float  ss[64 * SLDF];

    const int bx = blockIdx.x;
    const int h  = bx & 7;
    const int nw = (bx >> 3) & 63;
    const int b  = bx >> 9;
    const size_t base = ((size_t)(b * NWIN + nw) * LL) * PROJ_ + h * HD;
    const int tid = threadIdx.x;
    const int w   = tid >> 5;       // 0..3
    const int lane = tid & 31;
    const int mkind = g_mask_kind;

    {
        const __half hz = __float2half_rn(0.0f);
        for (int idx = tid; idx < 15 * QLDH; idx += 128) {
            const int o = 49 * QLDH + idx;
            qs[o] = hz; ks_[o] = hz; vs[o] = hz;
        }
        for (int idx = tid; idx < 64 * PLDH / 2; idx += 128)
            *reinterpret_cast<__half2*>(&ph[idx * 2]) = __half2half2(hz);
    }
    for (int idx = tid; idx < LL * 8; idx += 128) {
        const int r = idx >> 3;
        const int c = (idx & 7) << 2;
        const size_t g = base + (size_t)r * PROJ_ + c;
        *reinterpret_cast<uint2*>(&qs[r * QLDH + c])  = *reinterpret_cast<const uint2*>(&Q[g]);
        *reinterpret_cast<uint2*>(&ks_[r * QLDH + c]) = *reinterpret_cast<const uint2*>(&K[g]);
        *reinterpret_cast<uint2*>(&vs[r * QLDH + c])  = *reinterpret_cast<const uint2*>(&V[g]);
    }

    // Prefetch mask bits for softmax rows r = w + 4*ri
    unsigned int mbits = 0;
    {
        const size_t moff = (size_t)nw * LL * LL;
        const int c1ok = (lane + 32 < LL);
#pragma unroll
        for (int ri = 0; ri < 13; ri++) {
            const int r = w + 4 * ri;
            if (r < LL) {
                const size_t e0 = moff + (size_t)r * LL + lane;
                int m0, m1 = 0;
                if (mkind == 0) {
                    m0 = ((const int*)mask)[e0];
                    if (c1ok) m1 = ((const int*)mask)[e0 + 32];
                } else if (mkind == 1) {
                    m0 = ((const unsigned char*)mask)[e0];
                    if (c1ok) m1 = ((const unsigned char*)mask)[e0 + 32];
                } else {
                    m0 = (((const float*)mask)[e0] != 0.0f);
                    if (c1ok) m1 = (((const float*)mask)[e0 + 32] != 0.0f);
                }
                mbits |= (m0 ? 1u : 0u) << (2 * ri);
                mbits |= (m1 ? 1u : 0u) << (2 * ri + 1);
            }
        }
    }
    __syncthreads();

    // ---- S = Q @ K^T: warp w owns row tile w, all 4 col tiles ----
    {
        wmma::fragment<wmma::matrix_a, 16, 16, 16, __half, wmma::row_major> fa;
        wmma::fragment<wmma::matrix_b, 16, 16, 16, __half, wmma::col_major> fb;
        wmma::fragment<wmma::accumulator, 16, 16, 16, float> fc[4];
#pragma unroll
        for (int u = 0; u < 4; u++) wmma::fill_fragment(fc[u], 0.0f);

#pragma unroll
        for (int k = 0; k < 32; k += 16) {
            wmma::load_matrix_sync(fa, &qs[w * 16 * QLDH + k], QLDH);
#pragma unroll
            for (int u = 0; u < 4; u++) {
                wmma::load_matrix_sync(fb, &ks_[u * 16 * QLDH + k], QLDH);
                wmma::mma_sync(fc[u], fa, fb, fc[u]);
            }
        }
#pragma unroll
        for (int u = 0; u < 4; u++)
            wmma::store_matrix_sync(&ss[w * 16 * SLDF + u * 16], fc[u],
                                    SLDF, wmma::mem_row_major);
    }
    __syncthreads();

    // ---- Fused scale + mask + softmax -> P (half) ----
    {
        const float scale = 0.17677669529663687f;
        const int c1ok = (lane + 32 < LL);
#pragma unroll
        for (int ri = 0; ri < 13; ri++) {
            const int r = w + 4 * ri;
            if (r < LL) {
                float v0 = ss[r * SLDF + lane] * scale;
                if ((mbits >> (2 * ri)) & 1u) v0 = -1000.0f;
                float v1 = -3.0e38f;
                if (c1ok) {
                    v1 = ss[r * SLDF + lane + 32] * scale;
                    if ((mbits >> (2 * ri + 1)) & 1u) v1 = -1000.0f;
                }
                float m = fmaxf(v0, v1);
#pragma unroll
                for (int o = 16; o; o >>= 1) m = fmaxf(m, __shfl_xor_sync(0xffffffffu, m, o));
                const float e0 = __expf(v0 - m);
                const float e1 = c1ok ? __expf(v1 - m) : 0.0f;
                float s = e0 + e1;
#pragma unroll
                for (int o = 16; o; o >>= 1) s += __shfl_xor_sync(0xffffffffu, s, o);
                const float inv = 1.0f / s;
                ph[r * PLDH + lane] = __float2half_rn(e0 * inv);
                if (c1ok) ph[r * PLDH + lane + 32] = __float2half_rn(e1 * inv);
            }
        }
    }
    __syncthreads();

    // ---- Out = P @ V: warp w owns row tile w, both col tiles ----
    {
        wmma::fragment<wmma::matrix_a, 16, 16, 16, __half, wmma::row_major> pa;
        wmma::fragment<wmma::matrix_b, 16, 16, 16, __half, wmma::row_major> pb;
        wmma::fragment<wmma::accumulator, 16, 16, 16, float> fo[2];
        wmma::fill_fragment(fo[0], 0.0f);
        wmma::fill_fragment(fo[1], 0.0f);

#pragma unroll
        for (int k = 0; k < 64; k += 16) {
            wmma::load_matrix_sync(pa, &ph[w * 16 * PLDH + k], PLDH);
#pragma unroll
            for (int t = 0; t < 2; t++) {
                wmma::load_matrix_sync(pb, &vs[k * QLDH + t * 16], QLDH);
                wmma::mma_sync(fo[t], pa, pb, fo[t]);
            }
        }
#pragma unroll
        for (int t = 0; t < 2; t++)
            wmma::store_matrix_sync(&ss[w * 16 * SLDF + t * 16], fo[t], SLDF,
                                    wmma::mem_row_major);
    }
    __syncthreads();

    for (int idx = tid; idx < LL * 8; idx += 128) {
        const int r = idx >> 3;
        const int c = (idx & 7) << 2;
        union { __half2 h[2]; uint2 u; } pk;
        pk.h[0] = __floats2half2_rn(ss[r * SLDF + c],     ss[r * SLDF + c + 1]);
        pk.h[1] = __floats2half2_rn(ss[r * SLDF + c + 2], ss[r * SLDF + c + 3]);
        *reinterpret_cast<uint2*>(&O[base + (size_t)r * PROJ_ + c]) = pk.u;
    }
}

// ---------------------------------------------------------------------------
extern "C" void kernel_launch(void* const* d_in, const int* in_sizes, int n_in,
                              void* d_out, int out_size)
{
    const float* query = (const float*)d_in[0];
    const float* key_  = (const float*)d_in[1];
    const float* value = (const float*)d_in[2];
    const void*  mask  = d_in[3];
    const float* Wq = (const float*)d_in[4];
    const float* bq = (const float*)d_in[5];
    const float* Wk = (const float*)d_in[6];
    const float* bk = (const float*)d_in[7];
    const float* Wv = (const float*)d_in[8];
    const float* Ww = (const float*)d_in[9];
    const float* bw = (const float*)d_in[10];

    __half *qp, *kp, *vp, *wh;
    cudaGetSymbolAddress((void**)&qp, g_Q);
    cudaGetSymbolAddress((void**)&kp, g_K);
    cudaGetSymbolAddress((void**)&vp, g_V);
    cudaGetSymbolAddress((void**)&wh, g_Wh);

    __half* Wqh = wh;
    __half* Wkh = wh + DD * PROJ_;
    __half* Wvh = wh + 2 * DD * PROJ_;
    __half* Wwh = wh + 3 * DD * PROJ_;

    const int smemProj = 128 * 4 + (2 * 128 * ALDH + 2 * 32 * (128 + 8)) * 2; // 38400
    const int smemOut  = 16 * (64 + 4) * 4 + (2 * 128 * ALDH + 2 * 32 * (64 + 8)) * 2;
    cudaFuncSetAttribute(gemm_fp16_proj,
                         cudaFuncAttributeMaxDynamicSharedMemorySize, smemProj);
    cudaFuncSetAttribute(gemm_fp16_out,
                         cudaFuncAttributeMaxDynamicSharedMemorySize, smemOut);

    detect_mask_kind<<<1, 32>>>((const unsigned int*)mask);

    const int nel = DD * PROJ_;  // 49152
    round_all4<<<(4 * nel + 255) / 256, 256>>>(Wq, Wk, Wv, Ww, wh, nel);

    dim3 gproj(PROJ_ / 128, MTOT / 128);   // (2, 784)
    gemm_fp16_proj<<<gproj, 256, smemProj>>>(query, Wqh, bq,      qp, PROJ_, DD);
    gemm_fp16_proj<<<gproj, 256, smemProj>>>(key_,  Wkh, bk,      kp, PROJ_, DD);
    gemm_fp16_proj<<<gproj, 256, smemProj>>>(value, Wvh, nullptr, vp, PROJ_, DD);

    attn_fp16<<<BB * NWIN * HEADS, 128>>>(qp, kp, vp, mask, qp);

    dim3 gout(DD / 64, MTOT / 128);        // (3, 784)
    gemm_fp16_out<<<gout, 128, smemOut>>>(qp, Wwh, bw, (float*)d_out, DD, PROJ_);
}

// round 14
// speedup vs baseline: 1.1502x; 1.1502x over previous
#include <cuda_runtime.h>
#include <cstdint>
#include <cuda_fp16.h>
#include <mma.h>

using namespace nvcuda;

// Problem constants
#define BB    32
#define NWIN  64
#define LL    49
#define DD    192
#define PROJ_ 256
#define HEADS 8
#define HD    32
#define MTOT  (BB * NWIN * LL)   // 100352

#define ALDH 40      // A smem stride in halves
#define QLDH 40      // attention q/k/v stride (halves)
#define PLDH 72      // attention P stride (halves)
#define SLDF 68      // attention score/staging stride (floats)

// Scratch (device globals: allocation-free per harness rules)
__device__ __half g_Q[MTOT * PROJ_];
__device__ __half g_K[MTOT * PROJ_];
__device__ __half g_V[MTOT * PROJ_];
__device__ __half g_Wh[4 * DD * PROJ_];  // fp16-rounded weights (Wq|Wk|Wv|Ww)

// 0 = int32 mask, 1 = byte mask (bool/uint8), 2 = float32 mask
__device__ int g_mask_kind;

// ---------------------------------------------------------------------------
__global__ void detect_mask_kind(const unsigned int* __restrict__ m)
{
    const int lane = threadIdx.x;
    int not_int = 0, not_flt = 0;
    for (int i = lane; i < 256; i += 32) {
        unsigned int w = m[i];
        if (w > 1u) not_int = 1;
        if (w != 0u && w != 0x3F800000u) not_flt = 1;
    }
    not_int = __any_sync(0xffffffffu, not_int);
    not_flt = __any_sync(0xffffffffu, not_flt);
    if (lane == 0) {
        int kind;
        if (!not_int)      kind = 0;
        else if (!not_flt) kind = 2;
        else               kind = 1;
        g_mask_kind = kind;
    }
}

// ---------------------------------------------------------------------------
// One launch: round all 4 weight matrices to fp16 into contiguous g_Wh.
// ---------------------------------------------------------------------------
__global__ void round_all4(const float* __restrict__ s0, const float* __restrict__ s1,
                           const float* __restrict__ s2, const float* __restrict__ s3,
                           __half* __restrict__ dst, int n)
{
    const int i = blockIdx.x * 256 + threadIdx.x;
    if (i < 4 * n) {
        const int seg = i / n;
        const int off = i - seg * n;
        const float* s = (seg == 0) ? s0 : (seg == 1) ? s1 : (seg == 2) ? s2 : s3;
        dst[i] = __float2half_rn(s[off]);
    }
}

// ---------------------------------------------------------------------------
// cp.async helpers
// ---------------------------------------------------------------------------
__device__ __forceinline__ void cpa16(unsigned int saddr, const void* gptr)
{
    asm volatile("cp.async.ca.shared.global [%0], [%1], 16;\n" :: "r"(saddr), "l"(gptr));
}
__device__ __forceinline__ void cpa_commit()
{
    asm volatile("cp.async.commit_group;\n");
}
template <int N>
__device__ __forceinline__ void cpa_wait()
{
    asm volatile("cp.async.wait_group %0;\n" :: "n"(N));
}

// ---------------------------------------------------------------------------
// FP16 projection GEMM (R12 config): Ch[M,N] = half(A_f32[M,K] @ Bh[K,N] + bias)
// BM=128, BN=128, BK=32, 128 threads (2x2 warps, warp tile 64x64).
// A converted f32->half on smem store; B pre-rounded half via cp.async.
// ---------------------------------------------------------------------------
template <int BN_>
__global__ __launch_bounds__(128) void gemm_fp16_proj(
    const float* __restrict__ A, const __half* __restrict__ Bh,
    const float* __restrict__ bias, __half* __restrict__ C,
    int Nd, int Kd)
{
    constexpr int BLDH = BN_ + 8;
    constexpr int FJ   = BN_ / 32;
    constexpr int ABUFH = 128 * ALDH;
    constexpr int BBUFH = 32 * BLDH;

    extern __shared__ char smraw[];
    float*  BiasR = (float*)smraw;                         // BN_ f32
    __half* As    = (__half*)(smraw + BN_ * 4);            // 2*ABUFH halves
    __half* Bs    = As + 2 * ABUFH;                        // 2*BBUFH halves
    float*  Cs    = (float*)(smraw + BN_ * 4);             // staging alias

    const int tid = threadIdx.x;
    const int wid = tid >> 5;
    const int m0 = blockIdx.y * 128;
    const int n0 = blockIdx.x * BN_;

    const int lwr = (wid >> 1) * 64;
    const int lwc = (wid & 1) * (BN_ / 2);

    const int ar  = tid >> 3;             // 0..15
    const int ac4 = (tid & 7) << 2;       // 0,4,..28
    constexpr int TPRB = BN_ / 8;         // threads per B row (16B=8 halves)
    constexpr int RPPB = 128 / TPRB;
    constexpr int NPB  = 32 / RPPB;
    const int br  = tid / TPRB;
    const int bc8 = (tid % TPRB) << 3;

    const unsigned int bs_base = (unsigned int)__cvta_generic_to_shared(Bs);

    for (int c = tid; c < BN_; c += 128) BiasR[c] = bias ? bias[n0 + c] : 0.0f;

    wmma::fragment<wmma::matrix_a, 16, 16, 16, __half, wmma::row_major> fa[4];
    wmma::fragment<wmma::matrix_b, 16, 16, 16, __half, wmma::row_major> fb;
    wmma::fragment<wmma::accumulator, 16, 16, 16, float> fc[4][FJ];

#pragma unroll
    for (int i = 0; i < 4; i++)
#pragma unroll
        for (int j = 0; j < FJ; j++)
            wmma::fill_fragment(fc[i][j], 0.0f);

    const int niter = Kd / 32;

    auto load_A = [&](int buf, int k0) {
        __half* Ab = As + buf * ABUFH;
#pragma unroll
        for (int p = 0; p < 8; p++) {
            const int row = ar + p * 16;
            float4 v = *reinterpret_cast<const float4*>(
                &A[(size_t)(m0 + row) * Kd + k0 + ac4]);
            union { __half2 h[2]; uint2 u; } pk;
            pk.h[0] = __floats2half2_rn(v.x, v.y);
            pk.h[1] = __floats2half2_rn(v.z, v.w);
            *reinterpret_cast<uint2*>(&Ab[row * ALDH + ac4]) = pk.u;
        }
    };
    auto load_B = [&](int buf, int k0) {
        const unsigned int bsb = bs_base + (unsigned int)(buf * BBUFH) * 2u;
#pragma unroll
        for (int p = 0; p < NPB; p++) {
            const int row = br + p * RPPB;
            cpa16(bsb + (unsigned int)(row * BLDH + bc8) * 2u,
                  &Bh[(size_t)(k0 + row) * Nd + n0 + bc8]);
        }
        cpa_commit();
    };

    load_B(0, 0);
    load_A(0, 0);

    for (int it = 0; it < niter; it++) {
        const int buf = it & 1;
        if (it + 1 < niter) {
            load_B(buf ^ 1, (it + 1) * 32);
            load_A(buf ^ 1, (it + 1) * 32);
            cpa_wait<1>();
        } else {
            cpa_wait<0>();
        }
        __syncthreads();

        const __half* Ab = As + buf * ABUFH;
        const __half* Bb = Bs + buf * BBUFH;

#pragma unroll
        for (int ks = 0; ks < 32; ks += 16) {
#pragma unroll
            for (int i = 0; i < 4; i++)
                wmma::load_matrix_sync(fa[i], &Ab[(lwr + i * 16) * ALDH + ks], ALDH);
#pragma unroll
            for (int j = 0; j < FJ; j++) {
                wmma::load_matrix_sync(fb, &Bb[ks * BLDH + lwc + j * 16], BLDH);
#pragma unroll
                for (int i = 0; i < 4; i++)
                    wmma::mma_sync(fc[i][j], fa[i], fb, fc[i][j]);
            }
        }
        __syncthreads();
    }

    // Epilogue: stage 64-col halves in f32 smem, add bias, cvt to half, store.
    constexpr int NPASS = BN_ / 64;
#pragma unroll
    for (int jh = 0; jh < NPASS; jh++) {
        if (lwc == jh * 64 || BN_ == 64) {
#pragma unroll
            for (int j = 0; j < FJ; j++)
#pragma unroll
                for (int i = 0; i < 4; i++)
                    wmma::store_matrix_sync(
                        &Cs[(lwr + i * 16) * SLDF + (lwc - jh * 64) + j * 16],
                        fc[i][j], SLDF, wmma::mem_row_major);
        }
        __syncthreads();
        for (int idx = tid; idx < 128 * 16; idx += 128) {
            const int r  = idx >> 4;
            const int c4 = (idx & 15) << 2;
            const int cg = jh * 64 + c4;
            union { __half2 h[2]; uint2 u; } pk;
            pk.h[0] = __floats2half2_rn(Cs[r * SLDF + c4]     + BiasR[cg],
                                        Cs[r * SLDF + c4 + 1] + BiasR[cg + 1]);
            pk.h[1] = __floats2half2_rn(Cs[r * SLDF + c4 + 2] + BiasR[cg + 2],
                                        Cs[r * SLDF + c4 + 3] + BiasR[cg + 3]);
            *reinterpret_cast<uint2*>(&C[(size_t)(m0 + r) * Nd + n0 + cg]) = pk.u;
        }
        __syncthreads();
    }
}

// ---------------------------------------------------------------------------
// FP16 out GEMM (R12 config): C_f32[M,N] = Ah[M,K] @ Bh[K,N] + bias
// BM=128, BN=64, BK=32, 128 threads (2x2 warps, tile 64x32).
// ---------------------------------------------------------------------------
__global__ __launch_bounds__(128) void gemm_fp16_out(
    const __half* __restrict__ Ah, const __half* __restrict__ Bh,
    const float* __restrict__ bias, float* __restrict__ C,
    int Nd, int Kd)
{
    constexpr int BN_ = 64;
    constexpr int BLDH = BN_ + 8;
    constexpr int FJ   = 2;
    constexpr int ABUFH = 128 * ALDH;
    constexpr int BBUFH = 32 * BLDH;

    extern __shared__ char smraw[];
    float*  BiasT = (float*)smraw;                 // 16 x (BN_+4) f32
    __half* As    = (__half*)(smraw + 16 * (BN_ + 4) * 4);
    __half* Bs    = As + 2 * ABUFH;

    const int tid = threadIdx.x;
    const int wid = tid >> 5;
    const int m0 = blockIdx.y * 128;
    const int n0 = blockIdx.x * BN_;

    const int lwr = (wid >> 1) * 64;
    const int lwc = (wid & 1) * 32;

    const int aro = tid >> 2;             // 0..31
    const int ac8 = (tid & 3) << 3;       // 0,8,16,24
    const int br  = tid >> 3;             // 0..15
    const int bc8 = (tid & 7) << 3;

    const unsigned int as_base = (unsigned int)__cvta_generic_to_shared(As);
    const unsigned int bs_base = (unsigned int)__cvta_generic_to_shared(Bs);

    for (int idx = tid; idx < 16 * BN_; idx += 128) {
        const int r = idx / BN_;
        const int c = idx - r * BN_;
        BiasT[r * (BN_ + 4) + c] = bias ? bias[n0 + c] : 0.0f;
    }

    wmma::fragment<wmma::matrix_a, 16, 16, 16, __half, wmma::row_major> fa[4];
    wmma::fragment<wmma::matrix_b, 16, 16, 16, __half, wmma::row_major> fb;
    wmma::fragment<wmma::accumulator, 16, 16, 16, float> fc[4][FJ];

#pragma unroll
    for (int i = 0; i < 4; i++)
#pragma unroll
        for (int j = 0; j < FJ; j++)
            wmma::fill_fragment(fc[i][j], 0.0f);

    const int niter = Kd / 32;

    auto load_stage = [&](int buf, int k0) {
        const unsigned int asb = as_base + (unsigned int)(buf * ABUFH) * 2u;
        const unsigned int bsb = bs_base + (unsigned int)(buf * BBUFH) * 2u;
#pragma unroll
        for (int p = 0; p < 4; p++) {
            const int row = aro + p * 32;
            cpa16(asb + (unsigned int)(row * ALDH + ac8) * 2u,
                  &Ah[(size_t)(m0 + row) * Kd + k0 + ac8]);
        }
#pragma unroll
        for (int p = 0; p < 2; p++) {
            const int row = br + p * 16;
            cpa16(bsb + (unsigned int)(row * BLDH + bc8) * 2u,
                  &Bh[(size_t)(k0 + row) * Nd + n0 + bc8]);
        }
        cpa_commit();
    };

    load_stage(0, 0);

    for (int it = 0; it < niter; it++) {
        const int buf = it & 1;
        if (it + 1 < niter) {
            load_stage(buf ^ 1, (it + 1) * 32);
            cpa_wait<1>();
        } else {
            cpa_wait<0>();
        }
        __syncthreads();

        const __half* Ab = As + buf * ABUFH;
        const __half* Bb = Bs + buf * BBUFH;

#pragma unroll
        for (int ks = 0; ks < 32; ks += 16) {
#pragma unroll
            for (int i = 0; i < 4; i++)
                wmma::load_matrix_sync(fa[i], &Ab[(lwr + i * 16) * ALDH + ks], ALDH);
#pragma unroll
            for (int j = 0; j < FJ; j++) {
                wmma::load_matrix_sync(fb, &Bb[ks * BLDH + lwc + j * 16], BLDH);
#pragma unroll
                for (int i = 0; i < 4; i++)
                    wmma::mma_sync(fc[i][j], fa[i], fb, fc[i][j]);
            }
        }
        __syncthreads();
    }

    wmma::fragment<wmma::accumulator, 16, 16, 16, float> fbias;
#pragma unroll
    for (int j = 0; j < FJ; j++) {
        wmma::load_matrix_sync(fbias, &BiasT[lwc + j * 16], BN_ + 4, wmma::mem_row_major);
#pragma unroll
        for (int i = 0; i < 4; i++) {
#pragma unroll
            for (int t = 0; t < fbias.num_elements; t++)
                fc[i][j].x[t] += fbias.x[t];
            wmma::store_matrix_sync(
                &C[(size_t)(m0 + lwr + i * 16) * Nd + n0 + lwc + j * 16],
                fc[i][j], Nd, wmma::mem_row_major);
        }
    }
}

// ---------------------------------------------------------------------------
// FP16 WMMA window attention (R12 config, 256 threads / 8 warps).
// ---------------------------------------------------------------------------
__global__ __launch_bounds__(256) void attn_fp16(
    const __half* __restrict__ Q, const __half* __restrict__ K,
    const __half* __restrict__ V, const void* __restrict__ mask,
    __half* __restrict__ O)
{
    __shared__ __align__(16) __half qs[64 * QLDH];
    __shared__ __align__(16) __half ks_[64 * QLDH];
    __shared__ __align__(16) __half vs[64 * QLDH];
    __shared__ __align__(16) __half ph[64 * PLDH];
    __shared__ __align__(16) float  ss[64 * SLDF];

    const int bx = blockIdx.x;
    const int h  = bx & 7;
    const int nw = (bx >> 3) & 63;
    const int b  = bx >> 9;
    const size_t base = ((size_t)(b * NWIN + nw) * LL) * PROJ_ + h * HD;
    const int tid = threadIdx.x;
    const int w   = tid >> 5;
    const int lane = tid & 31;
    const int mkind = g_mask_kind;

    {
        const __half hz = __float2half_rn(0.0f);
        for (int idx = tid; idx < 15 * QLDH; idx += 256) {
            const int o = 49 * QLDH + idx;
            qs[o] = hz; ks_[o] = hz; vs[o] = hz;
        }
        for (int idx = tid; idx < 64 * PLDH / 2; idx += 256)
            *reinterpret_cast<__half2*>(&ph[idx * 2]) = __half2half2(hz);
    }
    for (int idx = tid; idx < LL * 8; idx += 256) {
        const int r = idx >> 3;
        const int c = (idx & 7) << 2;
        const size_t g = base + (size_t)r * PROJ_ + c;
        *reinterpret_cast<uint2*>(&qs[r * QLDH + c])  = *reinterpret_cast<const uint2*>(&Q[g]);
        *reinterpret_cast<uint2*>(&ks_[r * QLDH + c]) = *reinterpret_cast<const uint2*>(&K[g]);
        *reinterpret_cast<uint2*>(&vs[r * QLDH + c])  = *reinterpret_cast<const uint2*>(&V[g]);
    }

    // Prefetch mask bits (rows w + 8*ri)
    unsigned int mbits = 0;
    {
        const size_t moff = (size_t)nw * LL * LL;
        const int c1ok = (lane + 32 < LL);
#pragma unroll
        for (int ri = 0; ri < 7; ri++) {
            const int r = w + 8 * ri;
            if (r < LL) {
                const size_t e0 = moff + (size_t)r * LL + lane;
                int m0, m1 = 0;
                if (mkind == 0) {
                    m0 = ((const int*)mask)[e0];
                    if (c1ok) m1 = ((const int*)mask)[e0 + 32];
                } else if (mkind == 1) {
                    m0 = ((const unsigned char*)mask)[e0];
                    if (c1ok) m1 = ((const unsigned char*)mask)[e0 + 32];
                } else {
                    m0 = (((const float*)mask)[e0] != 0.0f);
                    if (c1ok) m1 = (((const float*)mask)[e0 + 32] != 0.0f);
                }
                mbits |= (m0 ? 1u : 0u) << (2 * ri);
                mbits |= (m1 ? 1u : 0u) << (2 * ri + 1);
            }
        }
    }
    __syncthreads();

    // ---- S = Q @ K^T (64x64x32 fp16), 16 tiles, 2 per warp ----
    {
        wmma::fragment<wmma::matrix_a, 16, 16, 16, __half, wmma::row_major> fa;
        wmma::fragment<wmma::matrix_b, 16, 16, 16, __half, wmma::col_major> fb;
        wmma::fragment<wmma::accumulator, 16, 16, 16, float> fc[2];
        wmma::fill_fragment(fc[0], 0.0f);
        wmma::fill_fragment(fc[1], 0.0f);

        const int ti = w >> 1;
        const int tj0 = (w & 1) * 2;

#pragma unroll
        for (int k = 0; k < 32; k += 16) {
            wmma::load_matrix_sync(fa, &qs[ti * 16 * QLDH + k], QLDH);
#pragma unroll
            for (int u = 0; u < 2; u++) {
                wmma::load_matrix_sync(fb, &ks_[(tj0 + u) * 16 * QLDH + k], QLDH);
                wmma::mma_sync(fc[u], fa, fb, fc[u]);
            }
        }
#pragma unroll
        for (int u = 0; u < 2; u++)
            wmma::store_matrix_sync(&ss[ti * 16 * SLDF + (tj0 + u) * 16], fc[u],
                                    SLDF, wmma::mem_row_major);
    }
    __syncthreads();

    // ---- Fused scale + mask + softmax -> P (half) ----
    {
        const float scale = 0.17677669529663687f;
        const int c1ok = (lane + 32 < LL);
#pragma unroll
        for (int ri = 0; ri < 7; ri++) {
            const int r = w + 8 * ri;
            if (r < LL) {
                float v0 = ss[r * SLDF + lane] * scale;
                if ((mbits >> (2 * ri)) & 1u) v0 = -1000.0f;
                float v1 = -3.0e38f;
                if (c1ok) {
                    v1 = ss[r * SLDF + lane + 32] * scale;
                    if ((mbits >> (2 * ri + 1)) & 1u) v1 = -1000.0f;
                }
                float m = fmaxf(v0, v1);
#pragma unroll
                for (int o = 16; o; o >>= 1) m = fmaxf(m, __shfl_xor_sync(0xffffffffu, m, o));
                const float e0 = __expf(v0 - m);
                const float e1 = c1ok ? __expf(v1 - m) : 0.0f;
                float s = e0 + e1;
#pragma unroll
                for (int o = 16; o; o >>= 1) s += __shfl_xor_sync(0xffffffffu, s, o);
                const float inv = 1.0f / s;
                ph[r * PLDH + lane] = __float2half_rn(e0 * inv);
                if (c1ok) ph[r * PLDH + lane + 32] = __float2half_rn(e1 * inv);
            }
        }
    }
    __syncthreads();

    // ---- Out = P @ V (64x32x64 fp16), 8 tiles, 1 per warp ----
    {
        wmma::fragment<wmma::matrix_a, 16, 16, 16, __half, wmma::row_major> pa;
        wmma::fragment<wmma::matrix_b, 16, 16, 16, __half, wmma::row_major> pb;
        wmma::fragment<wmma::accumulator, 16, 16, 16, float> fo;
        wmma::fill_fragment(fo, 0.0f);

        const int ti = w >> 1;
        const int tj = w & 1;

#pragma unroll
        for (int k = 0; k < 64; k += 16) {
            wmma::load_matrix_sync(pa, &ph[ti * 16 * PLDH + k], PLDH);
            wmma::load_matrix_sync(pb, &vs[k * QLDH + tj * 16], QLDH);
            wmma::mma_sync(fo, pa, pb, fo);
        }
        wmma::store_matrix_sync(&ss[ti * 16 * SLDF + tj * 16], fo, SLDF,
                                wmma::mem_row_major);
    }
    __syncthreads();

    // ---- Write valid 49x32 output as half ----
    for (int idx = tid; idx < LL * 8; idx += 256) {
        const int r = idx >> 3;
        const int c = (idx & 7) << 2;
        union { __half2 h[2]; uint2 u; } pk;
        pk.h[0] = __floats2half2_rn(ss[r * SLDF + c],     ss[r * SLDF + c + 1]);
        pk.h[1] = __floats2half2_rn(ss[r * SLDF + c + 2], ss[r * SLDF + c + 3]);
        *reinterpret_cast<uint2*>(&O[base + (size_t)r * PROJ_ + c]) = pk.u;
    }
}

// ---------------------------------------------------------------------------
extern "C" void kernel_launch(void* const* d_in, const int* in_sizes, int n_in,
                              void* d_out, int out_size)
{
    const float* query = (const float*)d_in[0];
    const float* key_  = (const float*)d_in[1];
    const float* value = (const float*)d_in[2];
    const void*  mask  = d_in[3];
    const float* Wq = (const float*)d_in[4];
    const float* bq = (const float*)d_in[5];
    const float* Wk = (const float*)d_in[6];
    const float* bk = (const float*)d_in[7];
    const float* Wv = (const float*)d_in[8];
    const float* Ww = (const float*)d_in[9];
    const float* bw = (const float*)d_in[10];

    __half *qp, *kp, *vp, *wh;
    cudaGetSymbolAddress((void**)&qp, g_Q);
    cudaGetSymbolAddress((void**)&kp, g_K);
    cudaGetSymbolAddress((void**)&vp, g_V);
    cudaGetSymbolAddress((void**)&wh, g_Wh);

    __half* Wqh = wh;
    __half* Wkh = wh + DD * PROJ_;
    __half* Wvh = wh + 2 * DD * PROJ_;
    __half* Wwh = wh + 3 * DD * PROJ_;

    const int smemProj = 128 * 4 + (2 * 128 * ALDH + 2 * 32 * (128 + 8)) * 2; // ~38.4KB
    const int smemOut  = 16 * (64 + 4) * 4 + (2 * 128 * ALDH + 2 * 32 * (64 + 8)) * 2;
    cudaFuncSetAttribute(gemm_fp16_proj<128>,
                         cudaFuncAttributeMaxDynamicSharedMemorySize, smemProj);
    cudaFuncSetAttribute(gemm_fp16_out,
                         cudaFuncAttributeMaxDynamicSharedMemorySize, smemOut);

    detect_mask_kind<<<1, 32>>>((const unsigned int*)mask);

    const int nel = DD * PROJ_;  // 49152
    round_all4<<<(4 * nel + 255) / 256, 256>>>(Wq, Wk, Wv, Ww, wh, nel);

    dim3 gproj(PROJ_ / 128, MTOT / 128);   // (2, 784)
    gemm_fp16_proj<128><<<gproj, 128, smemProj>>>(query, Wqh, bq,      qp, PROJ_, DD);
    gemm_fp16_proj<128><<<gproj, 128, smemProj>>>(key_,  Wkh, bk,      kp, PROJ_, DD);
    gemm_fp16_proj<128><<<gproj, 128, smemProj>>>(value, Wvh, nullptr, vp, PROJ_, DD);

    attn_fp16<<<BB * NWIN * HEADS, 256>>>(qp, kp, vp, mask, qp);

    dim3 gout(DD / 64, MTOT / 128);        // (3, 784)
    gemm_fp16_out<<<gout, 128, smemOut>>>(qp, Wwh, bw, (float*)d_out, DD, PROJ_);
}

// round 15
// speedup vs baseline: 1.2081x; 1.0503x over previous
#include <cuda_runtime.h>
#include <cstdint>
#include <cuda_fp16.h>
#include <mma.h>

using namespace nvcuda;

// Problem constants
#define BB    32
#define NWIN  64
#define LL    49
#define DD    192
#define PROJ_ 256
#define HEADS 8
#define HD    32
#define MTOT  (BB * NWIN * LL)   // 100352

#define ALDH 40      // A smem stride in halves
#define QLDH 40      // attention q/k/v stride (halves)
#define PLDH 72      // attention P stride (halves)
#define SLDF 68      // attention score/staging stride (floats)

// Scratch (device globals: allocation-free per harness rules)
__device__ __half g_Q[MTOT * PROJ_];
__device__ __half g_K[MTOT * PROJ_];
__device__ __half g_V[MTOT * PROJ_];
__device__ __half g_Wh[4 * DD * PROJ_];  // fp16-rounded weights (Wq|Wk|Wv|Ww)

// 0 = int32 mask, 1 = byte mask (bool/uint8), 2 = float32 mask
__device__ int g_mask_kind;

// ---------------------------------------------------------------------------
__global__ void detect_mask_kind(const unsigned int* __restrict__ m)
{
    const int lane = threadIdx.x;
    int not_int = 0, not_flt = 0;
    for (int i = lane; i < 256; i += 32) {
        unsigned int w = m[i];
        if (w > 1u) not_int = 1;
        if (w != 0u && w != 0x3F800000u) not_flt = 1;
    }
    not_int = __any_sync(0xffffffffu, not_int);
    not_flt = __any_sync(0xffffffffu, not_flt);
    if (lane == 0) {
        int kind;
        if (!not_int)      kind = 0;
        else if (!not_flt) kind = 2;
        else               kind = 1;
        g_mask_kind = kind;
    }
}

// ---------------------------------------------------------------------------
__global__ void round_all4(const float* __restrict__ s0, const float* __restrict__ s1,
                           const float* __restrict__ s2, const float* __restrict__ s3,
                           __half* __restrict__ dst, int n)
{
    const int i = blockIdx.x * 256 + threadIdx.x;
    if (i < 4 * n) {
        const int seg = i / n;
        const int off = i - seg * n;
        const float* s = (seg == 0) ? s0 : (seg == 1) ? s1 : (seg == 2) ? s2 : s3;
        dst[i] = __float2half_rn(s[off]);
    }
}

// ---------------------------------------------------------------------------
// cp.async helpers
// ---------------------------------------------------------------------------
__device__ __forceinline__ void cpa16(unsigned int saddr, const void* gptr)
{
    asm volatile("cp.async.ca.shared.global [%0], [%1], 16;\n" :: "r"(saddr), "l"(gptr));
}
__device__ __forceinline__ void cpa_commit()
{
    asm volatile("cp.async.commit_group;\n");
}
template <int N>
__device__ __forceinline__ void cpa_wait()
{
    asm volatile("cp.async.wait_group %0;\n" :: "n"(N));
}

// ---------------------------------------------------------------------------
// FP16 projection GEMM, software-pipelined A path:
// Ch[M,N] = half(A_f32[M,K] @ Bh[K,N] + bias)
// BM=128, BN=128, BK=32, 128 threads (2x2 warps, warp tile 64x64).
// A slab: LDG->regs at iteration top, cvt+STS AFTER compute (latency hidden).
// B slab: cp.async (pre-rounded half weights).
// ---------------------------------------------------------------------------
template <int BN_>
__global__ __launch_bounds__(128) void gemm_fp16_proj(
    const float* __restrict__ A, const __half* __restrict__ Bh,
    const float* __restrict__ bias, __half* __restrict__ C,
    int Nd, int Kd)
{
    constexpr int BLDH = BN_ + 8;
    constexpr int FJ   = BN_ / 32;
    constexpr int ABUFH = 128 * ALDH;
    constexpr int BBUFH = 32 * BLDH;

    extern __shared__ char smraw[];
    float*  BiasR = (float*)smraw;                         // BN_ f32
    __half* As    = (__half*)(smraw + BN_ * 4);            // 2*ABUFH halves
    __half* Bs    = As + 2 * ABUFH;                        // 2*BBUFH halves
    float*  Cs    = (float*)(smraw + BN_ * 4);             // staging alias

    const int tid = threadIdx.x;
    const int wid = tid >> 5;
    const int m0 = blockIdx.y * 128;
    const int n0 = blockIdx.x * BN_;

    const int lwr = (wid >> 1) * 64;
    const int lwc = (wid & 1) * (BN_ / 2);

    const int ar  = tid >> 3;             // 0..15
    const int ac4 = (tid & 7) << 2;       // 0,4,..28
    constexpr int TPRB = BN_ / 8;         // threads per B row (16B=8 halves)
    constexpr int RPPB = 128 / TPRB;
    constexpr int NPB  = 32 / RPPB;
    const int br  = tid / TPRB;
    const int bc8 = (tid % TPRB) << 3;

    const unsigned int bs_base = (unsigned int)__cvta_generic_to_shared(Bs);

    for (int c = tid; c < BN_; c += 128) BiasR[c] = bias ? bias[n0 + c] : 0.0f;

    wmma::fragment<wmma::matrix_a, 16, 16, 16, __half, wmma::row_major> fa[4];
    wmma::fragment<wmma::matrix_b, 16, 16, 16, __half, wmma::row_major> fb;
    wmma::fragment<wmma::accumulator, 16, 16, 16, float> fc[4][FJ];

#pragma unroll
    for (int i = 0; i < 4; i++)
#pragma unroll
        for (int j = 0; j < FJ; j++)
            wmma::fill_fragment(fc[i][j], 0.0f);

    const int niter = Kd / 32;

    float4 areg[8];

    auto ldg_A = [&](int k0) {
#pragma unroll
        for (int p = 0; p < 8; p++) {
            const int row = ar + p * 16;
            areg[p] = *reinterpret_cast<const float4*>(
                &A[(size_t)(m0 + row) * Kd + k0 + ac4]);
        }
    };
    auto sts_A = [&](int buf) {
        __half* Ab = As + buf * ABUFH;
#pragma unroll
        for (int p = 0; p < 8; p++) {
            const int row = ar + p * 16;
            union { __half2 h[2]; uint2 u; } pk;
            pk.h[0] = __floats2half2_rn(areg[p].x, areg[p].y);
            pk.h[1] = __floats2half2_rn(areg[p].z, areg[p].w);
            *reinterpret_cast<uint2*>(&Ab[row * ALDH + ac4]) = pk.u;
        }
    };
    auto load_B = [&](int buf, int k0) {
        const unsigned int bsb = bs_base + (unsigned int)(buf * BBUFH) * 2u;
#pragma unroll
        for (int p = 0; p < NPB; p++) {
            const int row = br + p * RPPB;
            cpa16(bsb + (unsigned int)(row * BLDH + bc8) * 2u,
                  &Bh[(size_t)(k0 + row) * Nd + n0 + bc8]);
        }
        cpa_commit();
    };

    // Prologue: stage 0 (A latency exposed once only)
    load_B(0, 0);
    ldg_A(0);
    sts_A(0);

    for (int it = 0; it < niter; it++) {
        const int buf = it & 1;
        if (it + 1 < niter) {
            ldg_A((it + 1) * 32);             // LDGs in flight across compute
            load_B(buf ^ 1, (it + 1) * 32);
            cpa_wait<1>();
        } else {
            cpa_wait<0>();
        }
        __syncthreads();

        const __half* Ab = As + buf * ABUFH;
        const __half* Bb = Bs + buf * BBUFH;

#pragma unroll
        for (int ks = 0; ks < 32; ks += 16) {
#pragma unroll
            for (int i = 0; i < 4; i++)
                wmma::load_matrix_sync(fa[i], &Ab[(lwr + i * 16) * ALDH + ks], ALDH);
#pragma unroll
            for (int j = 0; j < FJ; j++) {
                wmma::load_matrix_sync(fb, &Bb[ks * BLDH + lwc + j * 16], BLDH);
#pragma unroll
                for (int i = 0; i < 4; i++)
                    wmma::mma_sync(fc[i][j], fa[i], fb, fc[i][j]);
            }
        }

        if (it + 1 < niter) sts_A(buf ^ 1);   // after compute: LDG latency hidden
        __syncthreads();
    }

    // Epilogue: stage 64-col halves in f32 smem, add bias, cvt to half, store.
    constexpr int NPASS = BN_ / 64;
#pragma unroll
    for (int jh = 0; jh < NPASS; jh++) {
        if (lwc == jh * 64 || BN_ == 64) {
#pragma unroll
            for (int j = 0; j < FJ; j++)
#pragma unroll
                for (int i = 0; i < 4; i++)
                    wmma::store_matrix_sync(
                        &Cs[(lwr + i * 16) * SLDF + (lwc - jh * 64) + j * 16],
                        fc[i][j], SLDF, wmma::mem_row_major);
        }
        __syncthreads();
        for (int idx = tid; idx < 128 * 16; idx += 128) {
            const int r  = idx >> 4;
            const int c4 = (idx & 15) << 2;
            const int cg = jh * 64 + c4;
            union { __half2 h[2]; uint2 u; } pk;
            pk.h[0] = __floats2half2_rn(Cs[r * SLDF + c4]     + BiasR[cg],
                                        Cs[r * SLDF + c4 + 1] + BiasR[cg + 1]);
            pk.h[1] = __floats2half2_rn(Cs[r * SLDF + c4 + 2] + BiasR[cg + 2],
                                        Cs[r * SLDF + c4 + 3] + BiasR[cg + 3]);
            *reinterpret_cast<uint2*>(&C[(size_t)(m0 + r) * Nd + n0 + cg]) = pk.u;
        }
        __syncthreads();
    }
}

// ---------------------------------------------------------------------------
// FP16 out GEMM (unchanged, control): C_f32[M,N] = Ah[M,K] @ Bh[K,N] + bias
// ---------------------------------------------------------------------------
__global__ __launch_bounds__(128) void gemm_fp16_out(
    const __half* __restrict__ Ah, const __half* __restrict__ Bh,
    const float* __restrict__ bias, float* __restrict__ C,
    int Nd, int Kd)
{
    constexpr int BN_ = 64;
    constexpr int BLDH = BN_ + 8;
    constexpr int FJ   = 2;
    constexpr int ABUFH = 128 * ALDH;
    constexpr int BBUFH = 32 * BLDH;

    extern __shared__ char smraw[];
    float*  BiasT = (float*)smraw;                 // 16 x (BN_+4) f32
    __half* As    = (__half*)(smraw + 16 * (BN_ + 4) * 4);
    __half* Bs    = As + 2 * ABUFH;

    const int tid = threadIdx.x;
    const int wid = tid >> 5;
    const int m0 = blockIdx.y * 128;
    const int n0 = blockIdx.x * BN_;

    const int lwr = (wid >> 1) * 64;
    const int lwc = (wid & 1) * 32;

    const int aro = tid >> 2;
    const int ac8 = (tid & 3) << 3;
    const int br  = tid >> 3;
    const int bc8 = (tid & 7) << 3;

    const unsigned int as_base = (unsigned int)__cvta_generic_to_shared(As);
    const unsigned int bs_base = (unsigned int)__cvta_generic_to_shared(Bs);

    for (int idx = tid; idx < 16 * BN_; idx += 128) {
        const int r = idx / BN_;
        const int c = idx - r * BN_;
        BiasT[r * (BN_ + 4) + c] = bias ? bias[n0 + c] : 0.0f;
    }

    wmma::fragment<wmma::matrix_a, 16, 16, 16, __half, wmma::row_major> fa[4];
    wmma::fragment<wmma::matrix_b, 16, 16, 16, __half, wmma::row_major> fb;
    wmma::fragment<wmma::accumulator, 16, 16, 16, float> fc[4][FJ];

#pragma unroll
    for (int i = 0; i < 4; i++)
#pragma unroll
        for (int j = 0; j < FJ; j++)
            wmma::fill_fragment(fc[i][j], 0.0f);

    const int niter = Kd / 32;

    auto load_stage = [&](int buf, int k0) {
        const unsigned int asb = as_base + (unsigned int)(buf * ABUFH) * 2u;
        const unsigned int bsb = bs_base + (unsigned int)(buf * BBUFH) * 2u;
#pragma unroll
        for (int p = 0; p < 4; p++) {
            const int row = aro + p * 32;
            cpa16(asb + (unsigned int)(row * ALDH + ac8) * 2u,
                  &Ah[(size_t)(m0 + row) * Kd + k0 + ac8]);
        }
#pragma unroll
        for (int p = 0; p < 2; p++) {
            const int row = br + p * 16;
            cpa16(bsb + (unsigned int)(row * BLDH + bc8) * 2u,
                  &Bh[(size_t)(k0 + row) * Nd + n0 + bc8]);
        }
        cpa_commit();
    };

    load_stage(0, 0);

    for (int it = 0; it < niter; it++) {
        const int buf = it & 1;
        if (it + 1 < niter) {
            load_stage(buf ^ 1, (it + 1) * 32);
            cpa_wait<1>();
        } else {
            cpa_wait<0>();
        }
        __syncthreads();

        const __half* Ab = As + buf * ABUFH;
        const __half* Bb = Bs + buf * BBUFH;

#pragma unroll
        for (int ks = 0; ks < 32; ks += 16) {
#pragma unroll
            for (int i = 0; i < 4; i++)
                wmma::load_matrix_sync(fa[i], &Ab[(lwr + i * 16) * ALDH + ks], ALDH);
#pragma unroll
            for (int j = 0; j < FJ; j++) {
                wmma::load_matrix_sync(fb, &Bb[ks * BLDH + lwc + j * 16], BLDH);
#pragma unroll
                for (int i = 0; i < 4; i++)
                    wmma::mma_sync(fc[i][j], fa[i], fb, fc[i][j]);
            }
        }
        __syncthreads();
    }

    wmma::fragment<wmma::accumulator, 16, 16, 16, float> fbias;
#pragma unroll
    for (int j = 0; j < FJ; j++) {
        wmma::load_matrix_sync(fbias, &BiasT[lwc + j * 16], BN_ + 4, wmma::mem_row_major);
#pragma unroll
        for (int i = 0; i < 4; i++) {
#pragma unroll
            for (int t = 0; t < fbias.num_elements; t++)
                fc[i][j].x[t] += fbias.x[t];
            wmma::store_matrix_sync(
                &C[(size_t)(m0 + lwr + i * 16) * Nd + n0 + lwc + j * 16],
                fc[i][j], Nd, wmma::mem_row_major);
        }
    }
}

// ---------------------------------------------------------------------------
// FP16 WMMA window attention, smem-aliased: ph overlays qs+ks (dead after
// the S MMA). Total smem 32768B -> more CTAs/SM.
// Layout: [0,5120) qs | [5120,10240) ks | [10240,15360) vs | [15360,32768) ss
//         ph = [0, 9216) (alias, used from softmax onward)
// ---------------------------------------------------------------------------
__global__ __launch_bounds__(256) void attn_fp16(
    const __half* __restrict__ Q, const __half* __restrict__ K,
    const __half* __restrict__ V, const void* __restrict__ mask,
    __half* __restrict__ O)
{
    __shared__ __align__(16) char sm[32768];
    __half* qs  = (__half*)(sm);
    __half* ks_ = (__half*)(sm + 5120);
    __half* vs  = (__half*)(sm + 10240);
    float*  ss  = (float*)(sm + 15360);
    __half* ph  = (__half*)(sm);           // alias over qs+ks

    const int bx = blockIdx.x;
    const int h  = bx & 7;
    const int nw = (bx >> 3) & 63;
    const int b  = bx >> 9;
    const size_t base = ((size_t)(b * NWIN + nw) * LL) * PROJ_ + h * HD;
    const int tid = threadIdx.x;
    const int w   = tid >> 5;
    const int lane = tid & 31;
    const int mkind = g_mask_kind;

    {
        const __half hz = __float2half_rn(0.0f);
        for (int idx = tid; idx < 15 * QLDH; idx += 256) {
            const int o = 49 * QLDH + idx;
            qs[o] = hz; ks_[o] = hz; vs[o] = hz;
        }
    }
    for (int idx = tid; idx < LL * 8; idx += 256) {
        const int r = idx >> 3;
        const int c = (idx & 7) << 2;
        const size_t g = base + (size_t)r * PROJ_ + c;
        *reinterpret_cast<uint2*>(&qs[r * QLDH + c])  = *reinterpret_cast<const uint2*>(&Q[g]);
        *reinterpret_cast<uint2*>(&ks_[r * QLDH + c]) = *reinterpret_cast<const uint2*>(&K[g]);
        *reinterpret_cast<uint2*>(&vs[r * QLDH + c])  = *reinterpret_cast<const uint2*>(&V[g]);
    }

    // Prefetch mask bits (rows w + 8*ri)
    unsigned int mbits = 0;
    {
        const size_t moff = (size_t)nw * LL * LL;
        const int c1ok = (lane + 32 < LL);
#pragma unroll
        for (int ri = 0; ri < 7; ri++) {
            const int r = w + 8 * ri;
            if (r < LL) {
                const size_t e0 = moff + (size_t)r * LL + lane;
                int m0, m1 = 0;
                if (mkind == 0) {
                    m0 = ((const int*)mask)[e0];
                    if (c1ok) m1 = ((const int*)mask)[e0 + 32];
                } else if (mkind == 1) {
                    m0 = ((const unsigned char*)mask)[e0];
                    if (c1ok) m1 = ((const unsigned char*)mask)[e0 + 32];
                } else {
                    m0 = (((const float*)mask)[e0] != 0.0f);
                    if (c1ok) m1 = (((const float*)mask)[e0 + 32] != 0.0f);
                }
                mbits |= (m0 ? 1u : 0u) << (2 * ri);
                mbits |= (m1 ? 1u : 0u) << (2 * ri + 1);
            }
        }
    }
    __syncthreads();

    // ---- S = Q @ K^T (64x64x32 fp16), 16 tiles, 2 per warp ----
    {
        wmma::fragment<wmma::matrix_a, 16, 16, 16, __half, wmma::row_major> fa;
        wmma::fragment<wmma::matrix_b, 16, 16, 16, __half, wmma::col_major> fb;
        wmma::fragment<wmma::accumulator, 16, 16, 16, float> fc[2];
        wmma::fill_fragment(fc[0], 0.0f);
        wmma::fill_fragment(fc[1], 0.0f);

        const int ti = w >> 1;
        const int tj0 = (w & 1) * 2;

#pragma unroll
        for (int k = 0; k < 32; k += 16) {
            wmma::load_matrix_sync(fa, &qs[ti * 16 * QLDH + k], QLDH);
#pragma unroll
            for (int u = 0; u < 2; u++) {
                wmma::load_matrix_sync(fb, &ks_[(tj0 + u) * 16 * QLDH + k], QLDH);
                wmma::mma_sync(fc[u], fa, fb, fc[u]);
            }
        }
#pragma unroll
        for (int u = 0; u < 2; u++)
            wmma::store_matrix_sync(&ss[ti * 16 * SLDF + (tj0 + u) * 16], fc[u],
                                    SLDF, wmma::mem_row_major);
    }
    __syncthreads();   // after this barrier qs/ks are dead -> ph may be written

    // ---- Fused scale + mask + softmax -> P (half, aliased region) ----
    // Valid cols 0..48 written with probs; pad cols 49..63 zeroed here
    // (needed because V pad rows are 0 but P pad cols must be finite*0).
    {
        const float scale = 0.17677669529663687f;
        const int c1ok = (lane + 32 < LL);
#pragma unroll
        for (int ri = 0; ri < 7; ri++) {
            const int r = w + 8 * ri;
            if (r < LL) {
                float v0 = ss[r * SLDF + lane] * scale;
                if ((mbits >> (2 * ri)) & 1u) v0 = -1000.0f;
                float v1 = -3.0e38f;
                if (c1ok) {
                    v1 = ss[r * SLDF + lane + 32] * scale;
                    if ((mbits >> (2 * ri + 1)) & 1u) v1 = -1000.0f;
                }
                float m = fmaxf(v0, v1);
#pragma unroll
                for (int o = 16; o; o >>= 1) m = fmaxf(m, __shfl_xor_sync(0xffffffffu, m, o));
                const float e0 = __expf(v0 - m);
                const float e1 = c1ok ? __expf(v1 - m) : 0.0f;
                float s = e0 + e1;
#pragma unroll
                for (int o = 16; o; o >>= 1) s += __shfl_xor_sync(0xffffffffu, s, o);
                const float inv = 1.0f / s;
                ph[r * PLDH + lane] = __float2half_rn(e0 * inv);
                // second half: valid cols 32..48 get probs, pad cols 49..63 zero
                ph[r * PLDH + 32 + lane] =
                    c1ok ? __float2half_rn(e1 * inv) : __float2half_rn(0.0f);
            }
        }
        // P pad rows 49..63: zero them too (cheap; avoids any NaN surprises)
        for (int idx = tid; idx < 15 * PLDH / 2; idx += 256) {
            const int o = 49 * PLDH + idx * 2;
            *reinterpret_cast<__half2*>(&ph[o]) = __half2half2(__float2half_rn(0.0f));
        }
    }
    __syncthreads();

    // ---- Out = P @ V (64x32x64 fp16), 8 tiles, 1 per warp ----
    {
        wmma::fragment<wmma::matrix_a, 16, 16, 16, __half, wmma::row_major> pa;
        wmma::fragment<wmma::matrix_b, 16, 16, 16, __half, wmma::row_major> pb;
        wmma::fragment<wmma::accumulator, 16, 16, 16, float> fo;
        wmma::fill_fragment(fo, 0.0f);

        const int ti = w >> 1;
        const int tj = w & 1;

#pragma unroll
        for (int k = 0; k < 64; k += 16) {
            wmma::load_matrix_sync(pa, &ph[ti * 16 * PLDH + k], PLDH);
            wmma::load_matrix_sync(pb, &vs[k * QLDH + tj * 16], QLDH);
            wmma::mma_sync(fo, pa, pb, fo);
        }
        wmma::store_matrix_sync(&ss[ti * 16 * SLDF + tj * 16], fo, SLDF,
                                wmma::mem_row_major);
    }
    __syncthreads();

    // ---- Write valid 49x32 output as half ----
    for (int idx = tid; idx < LL * 8; idx += 256) {
        const int r = idx >> 3;
        const int c = (idx & 7) << 2;
        union { __half2 h[2]; uint2 u; } pk;
        pk.h[0] = __floats2half2_rn(ss[r * SLDF + c],     ss[r * SLDF + c + 1]);
        pk.h[1] = __floats2half2_rn(ss[r * SLDF + c + 2], ss[r * SLDF + c + 3]);
        *reinterpret_cast<uint2*>(&O[base + (size_t)r * PROJ_ + c]) = pk.u;
    }
}

// ---------------------------------------------------------------------------
extern "C" void kernel_launch(void* const* d_in, const int* in_sizes, int n_in,
                              void* d_out, int out_size)
{
    const float* query = (const float*)d_in[0];
    const float* key_  = (const float*)d_in[1];
    const float* value = (const float*)d_in[2];
    const void*  mask  = d_in[3];
    const float* Wq = (const float*)d_in[4];
    const float* bq = (const float*)d_in[5];
    const float* Wk = (const float*)d_in[6];
    const float* bk = (const float*)d_in[7];
    const float* Wv = (const float*)d_in[8];
    const float* Ww = (const float*)d_in[9];
    const float* bw = (const float*)d_in[10];

    __half *qp, *kp, *vp, *wh;
    cudaGetSymbolAddress((void**)&qp, g_Q);
    cudaGetSymbolAddress((void**)&kp, g_K);
    cudaGetSymbolAddress((void**)&vp, g_V);
    cudaGetSymbolAddress((void**)&wh, g_Wh);

    __half* Wqh = wh;
    __half* Wkh = wh + DD * PROJ_;
    __half* Wvh = wh + 2 * DD * PROJ_;
    __half* Wwh = wh + 3 * DD * PROJ_;

    const int smemProj = 128 * 4 + (2 * 128 * ALDH + 2 * 32 * (128 + 8)) * 2; // ~38.4KB
    const int smemOut  = 16 * (64 + 4) * 4 + (2 * 128 * ALDH + 2 * 32 * (64 + 8)) * 2;
    cudaFuncSetAttribute(gemm_fp16_proj<128>,
                         cudaFuncAttributeMaxDynamicSharedMemorySize, smemProj);
    cudaFuncSetAttribute(gemm_fp16_out,
                         cudaFuncAttributeMaxDynamicSharedMemorySize, smemOut);

    detect_mask_kind<<<1, 32>>>((const unsigned int*)mask);

    const int nel = DD * PROJ_;  // 49152
    round_all4<<<(4 * nel + 255) / 256, 256>>>(Wq, Wk, Wv, Ww, wh, nel);

    dim3 gproj(PROJ_ / 128, MTOT / 128);   // (2, 784)
    gemm_fp16_proj<128><<<gproj, 128, smemProj>>>(query, Wqh, bq,      qp, PROJ_, DD);
    gemm_fp16_proj<128><<<gproj, 128, smemProj>>>(key_,  Wkh, bk,      kp, PROJ_, DD);
    gemm_fp16_proj<128><<<gproj, 128, smemProj>>>(value, Wvh, nullptr, vp, PROJ_, DD);

    attn_fp16<<<BB * NWIN * HEADS, 256>>>(qp, kp, vp, mask, qp);

    dim3 gout(DD / 64, MTOT / 128);        // (3, 784)
    gemm_fp16_out<<<gout, 128, smemOut>>>(qp, Wwh, bw, (float*)d_out, DD, PROJ_);
}

// round 16
// speedup vs baseline: 1.2268x; 1.0154x over previous
#include <cuda_runtime.h>
#include <cstdint>
#include <cuda_fp16.h>
#include <mma.h>

using namespace nvcuda;

// Problem constants
#define BB    32
#define NWIN  64
#define LL    49
#define DD    192
#define PROJ_ 256
#define HEADS 8
#define HD    32
#define MTOT  (BB * NWIN * LL)   // 100352

#define ALDH 40      // A smem stride in halves
#define QLDH 40      // attention q/k/v stride (halves)
#define PLDH 72      // attention P stride (halves)
#define SLDF 68      // attention score/staging stride (floats)

// Scratch (device globals: allocation-free per harness rules)
__device__ __half g_Q[MTOT * PROJ_];
__device__ __half g_K[MTOT * PROJ_];
__device__ __half g_V[MTOT * PROJ_];
__device__ __half g_Wh[4 * DD * PROJ_];  // fp16-rounded weights (Wq|Wk|Wv|Ww)

// 0 = int32 mask, 1 = byte mask (bool/uint8), 2 = float32 mask
__device__ int g_mask_kind;

// ---------------------------------------------------------------------------
__global__ void detect_mask_kind(const unsigned int* __restrict__ m)
{
    const int lane = threadIdx.x;
    int not_int = 0, not_flt = 0;
    for (int i = lane; i < 256; i += 32) {
        unsigned int w = m[i];
        if (w > 1u) not_int = 1;
        if (w != 0u && w != 0x3F800000u) not_flt = 1;
    }
    not_int = __any_sync(0xffffffffu, not_int);
    not_flt = __any_sync(0xffffffffu, not_flt);
    if (lane == 0) {
        int kind;
        if (!not_int)      kind = 0;
        else if (!not_flt) kind = 2;
        else               kind = 1;
        g_mask_kind = kind;
    }
}

// ---------------------------------------------------------------------------
__global__ void round_all4(const float* __restrict__ s0, const float* __restrict__ s1,
                           const float* __restrict__ s2, const float* __restrict__ s3,
                           __half* __restrict__ dst, int n)
{
    const int i = blockIdx.x * 256 + threadIdx.x;
    if (i < 4 * n) {
        const int seg = i / n;
        const int off = i - seg * n;
        const float* s = (seg == 0) ? s0 : (seg == 1) ? s1 : (seg == 2) ? s2 : s3;
        dst[i] = __float2half_rn(s[off]);
    }
}

// ---------------------------------------------------------------------------
// cp.async helpers
// ---------------------------------------------------------------------------
__device__ __forceinline__ void cpa16(unsigned int saddr, const void* gptr)
{
    asm volatile("cp.async.ca.shared.global [%0], [%1], 16;\n" :: "r"(saddr), "l"(gptr));
}
__device__ __forceinline__ void cpa_commit()
{
    asm volatile("cp.async.commit_group;\n");
}
template <int N>
__device__ __forceinline__ void cpa_wait()
{
    asm volatile("cp.async.wait_group %0;\n" :: "n"(N));
}

// ---------------------------------------------------------------------------
// Fused FP16 projection GEMMs (Q|K|V selected by blockIdx.z):
// Ch[M,N] = half(A_f32[M,K] @ Bh[K,N] + bias)
// BM=128, BN=128, BK=32, 128 threads (2x2 warps, warp tile 64x64),
// software-pipelined A (LDG at top, cvt+STS after compute), cp.async B.
// __launch_bounds__(128,3): cap regs for 3 CTAs/SM.
// ---------------------------------------------------------------------------
__global__ __launch_bounds__(128, 3) void gemm_fp16_proj3(
    const float* __restrict__ A0, const float* __restrict__ A1,
    const float* __restrict__ A2,
    const __half* __restrict__ WhBase,
    const float* __restrict__ bq, const float* __restrict__ bk,
    __half* __restrict__ C0, __half* __restrict__ C1, __half* __restrict__ C2,
    int Nd, int Kd)
{
    constexpr int BN_ = 128;
    constexpr int BLDH = BN_ + 8;
    constexpr int FJ   = BN_ / 32;
    constexpr int ABUFH = 128 * ALDH;
    constexpr int BBUFH = 32 * BLDH;

    extern __shared__ char smraw[];
    float*  BiasR = (float*)smraw;                         // BN_ f32
    __half* As    = (__half*)(smraw + BN_ * 4);            // 2*ABUFH halves
    __half* Bs    = As + 2 * ABUFH;                        // 2*BBUFH halves
    float*  Cs    = (float*)(smraw + BN_ * 4);             // staging alias

    const int z = blockIdx.z;
    const float* A   = (z == 0) ? A0 : (z == 1) ? A1 : A2;
    const __half* Bh = WhBase + (size_t)z * DD * PROJ_;
    const float* bias = (z == 0) ? bq : (z == 1) ? bk : nullptr;
    __half* C = (z == 0) ? C0 : (z == 1) ? C1 : C2;

    const int tid = threadIdx.x;
    const int wid = tid >> 5;
    const int m0 = blockIdx.y * 128;
    const int n0 = blockIdx.x * BN_;

    const int lwr = (wid >> 1) * 64;
    const int lwc = (wid & 1) * 64;

    const int ar  = tid >> 3;             // 0..15
    const int ac4 = (tid & 7) << 2;       // 0,4,..28
    constexpr int TPRB = BN_ / 8;
    constexpr int RPPB = 128 / TPRB;
    constexpr int NPB  = 32 / RPPB;
    const int br  = tid / TPRB;
    const int bc8 = (tid % TPRB) << 3;

    const unsigned int bs_base = (unsigned int)__cvta_generic_to_shared(Bs);

    for (int c = tid; c < BN_; c += 128) BiasR[c] = bias ? bias[n0 + c] : 0.0f;

    wmma::fragment<wmma::matrix_a, 16, 16, 16, __half, wmma::row_major> fa[4];
    wmma::fragment<wmma::matrix_b, 16, 16, 16, __half, wmma::row_major> fb;
    wmma::fragment<wmma::accumulator, 16, 16, 16, float> fc[4][FJ];

#pragma unroll
    for (int i = 0; i < 4; i++)
#pragma unroll
        for (int j = 0; j < FJ; j++)
            wmma::fill_fragment(fc[i][j], 0.0f);

    const int niter = Kd / 32;

    float4 areg[8];

    auto ldg_A = [&](int k0) {
#pragma unroll
        for (int p = 0; p < 8; p++) {
            const int row = ar + p * 16;
            areg[p] = *reinterpret_cast<const float4*>(
                &A[(size_t)(m0 + row) * Kd + k0 + ac4]);
        }
    };
    auto sts_A = [&](int buf) {
        __half* Ab = As + buf * ABUFH;
#pragma unroll
        for (int p = 0; p < 8; p++) {
            const int row = ar + p * 16;
            union { __half2 h[2]; uint2 u; } pk;
            pk.h[0] = __floats2half2_rn(areg[p].x, areg[p].y);
            pk.h[1] = __floats2half2_rn(areg[p].z, areg[p].w);
            *reinterpret_cast<uint2*>(&Ab[row * ALDH + ac4]) = pk.u;
        }
    };
    auto load_B = [&](int buf, int k0) {
        const unsigned int bsb = bs_base + (unsigned int)(buf * BBUFH) * 2u;
#pragma unroll
        for (int p = 0; p < NPB; p++) {
            const int row = br + p * RPPB;
            cpa16(bsb + (unsigned int)(row * BLDH + bc8) * 2u,
                  &Bh[(size_t)(k0 + row) * Nd + n0 + bc8]);
        }
        cpa_commit();
    };

    load_B(0, 0);
    ldg_A(0);
    sts_A(0);

    for (int it = 0; it < niter; it++) {
        const int buf = it & 1;
        if (it + 1 < niter) {
            ldg_A((it + 1) * 32);
            load_B(buf ^ 1, (it + 1) * 32);
            cpa_wait<1>();
        } else {
            cpa_wait<0>();
        }
        __syncthreads();

        const __half* Ab = As + buf * ABUFH;
        const __half* Bb = Bs + buf * BBUFH;

#pragma unroll
        for (int ks = 0; ks < 32; ks += 16) {
#pragma unroll
            for (int i = 0; i < 4; i++)
                wmma::load_matrix_sync(fa[i], &Ab[(lwr + i * 16) * ALDH + ks], ALDH);
#pragma unroll
            for (int j = 0; j < FJ; j++) {
                wmma::load_matrix_sync(fb, &Bb[ks * BLDH + lwc + j * 16], BLDH);
#pragma unroll
                for (int i = 0; i < 4; i++)
                    wmma::mma_sync(fc[i][j], fa[i], fb, fc[i][j]);
            }
        }

        if (it + 1 < niter) sts_A(buf ^ 1);
        __syncthreads();
    }

    // Epilogue: two 64-col passes through f32 staging, add bias, store half.
#pragma unroll
    for (int jh = 0; jh < 2; jh++) {
        if (lwc == jh * 64) {
#pragma unroll
            for (int j = 0; j < FJ; j++)
#pragma unroll
                for (int i = 0; i < 4; i++)
                    wmma::store_matrix_sync(
                        &Cs[(lwr + i * 16) * SLDF + j * 16],
                        fc[i][j], SLDF, wmma::mem_row_major);
        }
        __syncthreads();
        for (int idx = tid; idx < 128 * 16; idx += 128) {
            const int r  = idx >> 4;
            const int c4 = (idx & 15) << 2;
            const int cg = jh * 64 + c4;
            union { __half2 h[2]; uint2 u; } pk;
            pk.h[0] = __floats2half2_rn(Cs[r * SLDF + c4]     + BiasR[cg],
                                        Cs[r * SLDF + c4 + 1] + BiasR[cg + 1]);
            pk.h[1] = __floats2half2_rn(Cs[r * SLDF + c4 + 2] + BiasR[cg + 2],
                                        Cs[r * SLDF + c4 + 3] + BiasR[cg + 3]);
            *reinterpret_cast<uint2*>(&C[(size_t)(m0 + r) * Nd + n0 + cg]) = pk.u;
        }
        __syncthreads();
    }
}

// ---------------------------------------------------------------------------
// FP16 out GEMM (unchanged): C_f32[M,N] = Ah[M,K] @ Bh[K,N] + bias
// ---------------------------------------------------------------------------
__global__ __launch_bounds__(128) void gemm_fp16_out(
    const __half* __restrict__ Ah, const __half* __restrict__ Bh,
    const float* __restrict__ bias, float* __restrict__ C,
    int Nd, int Kd)
{
    constexpr int BN_ = 64;
    constexpr int BLDH = BN_ + 8;
    constexpr int FJ   = 2;
    constexpr int ABUFH = 128 * ALDH;
    constexpr int BBUFH = 32 * BLDH;

    extern __shared__ char smraw[];
    float*  BiasT = (float*)smraw;                 // 16 x (BN_+4) f32
    __half* As    = (__half*)(smraw + 16 * (BN_ + 4) * 4);
    __half* Bs    = As + 2 * ABUFH;

    const int tid = threadIdx.x;
    const int wid = tid >> 5;
    const int m0 = blockIdx.y * 128;
    const int n0 = blockIdx.x * BN_;

    const int lwr = (wid >> 1) * 64;
    const int lwc = (wid & 1) * 32;

    const int aro = tid >> 2;
    const int ac8 = (tid & 3) << 3;
    const int br  = tid >> 3;
    const int bc8 = (tid & 7) << 3;

    const unsigned int as_base = (unsigned int)__cvta_generic_to_shared(As);
    const unsigned int bs_base = (unsigned int)__cvta_generic_to_shared(Bs);

    for (int idx = tid; idx < 16 * BN_; idx += 128) {
        const int r = idx / BN_;
        const int c = idx - r * BN_;
        BiasT[r * (BN_ + 4) + c] = bias ? bias[n0 + c] : 0.0f;
    }

    wmma::fragment<wmma::matrix_a, 16, 16, 16, __half, wmma::row_major> fa[4];
    wmma::fragment<wmma::matrix_b, 16, 16, 16, __half, wmma::row_major> fb;
    wmma::fragment<wmma::accumulator, 16, 16, 16, float> fc[4][FJ];

#pragma unroll
    for (int i = 0; i < 4; i++)
#pragma unroll
        for (int j = 0; j < FJ; j++)
            wmma::fill_fragment(fc[i][j], 0.0f);

    const int niter = Kd / 32;

    auto load_stage = [&](int buf, int k0) {
        const unsigned int asb = as_base + (unsigned int)(buf * ABUFH) * 2u;
        const unsigned int bsb = bs_base + (unsigned int)(buf * BBUFH) * 2u;
#pragma unroll
        for (int p = 0; p < 4; p++) {
            const int row = aro + p * 32;
            cpa16(asb + (unsigned int)(row * ALDH + ac8) * 2u,
                  &Ah[(size_t)(m0 + row) * Kd + k0 + ac8]);
        }
#pragma unroll
        for (int p = 0; p < 2; p++) {
            const int row = br + p * 16;
            cpa16(bsb + (unsigned int)(row * BLDH + bc8) * 2u,
                  &Bh[(size_t)(k0 + row) * Nd + n0 + bc8]);
        }
        cpa_commit();
    };

    load_stage(0, 0);

    for (int it = 0; it < niter; it++) {
        const int buf = it & 1;
        if (it + 1 < niter) {
            load_stage(buf ^ 1, (it + 1) * 32);
            cpa_wait<1>();
        } else {
            cpa_wait<0>();
        }
        __syncthreads();

        const __half* Ab = As + buf * ABUFH;
        const __half* Bb = Bs + buf * BBUFH;

#pragma unroll
        for (int ks = 0; ks < 32; ks += 16) {
#pragma unroll
            for (int i = 0; i < 4; i++)
                wmma::load_matrix_sync(fa[i], &Ab[(lwr + i * 16) * ALDH + ks], ALDH);
#pragma unroll
            for (int j = 0; j < FJ; j++) {
                wmma::load_matrix_sync(fb, &Bb[ks * BLDH + lwc + j * 16], BLDH);
#pragma unroll
                for (int i = 0; i < 4; i++)
                    wmma::mma_sync(fc[i][j], fa[i], fb, fc[i][j]);
            }
        }
        __syncthreads();
    }

    wmma::fragment<wmma::accumulator, 16, 16, 16, float> fbias;
#pragma unroll
    for (int j = 0; j < FJ; j++) {
        wmma::load_matrix_sync(fbias, &BiasT[lwc + j * 16], BN_ + 4, wmma::mem_row_major);
#pragma unroll
        for (int i = 0; i < 4; i++) {
#pragma unroll
            for (int t = 0; t < fbias.num_elements; t++)
                fc[i][j].x[t] += fbias.x[t];
            wmma::store_matrix_sync(
                &C[(size_t)(m0 + lwr + i * 16) * Nd + n0 + lwc + j * 16],
                fc[i][j], Nd, wmma::mem_row_major);
        }
    }
}

// ---------------------------------------------------------------------------
// FP16 WMMA window attention, smem-aliased, max-free softmax.
// Layout: [0,5120) qs | [5120,10240) ks | [10240,15360) vs | [15360,32768) ss
//         ph = [0, 9216) (alias over qs+ks, used from softmax onward)
// ---------------------------------------------------------------------------
__global__ __launch_bounds__(256) void attn_fp16(
    const __half* __restrict__ Q, const __half* __restrict__ K,
    const __half* __restrict__ V, const void* __restrict__ mask,
    __half* __restrict__ O)
{
    __shared__ __align__(16) char sm[32768];
    __half* qs  = (__half*)(sm);
    __half* ks_ = (__half*)(sm + 5120);
    __half* vs  = (__half*)(sm + 10240);
    float*  ss  = (float*)(sm + 15360);
    __half* ph  = (__half*)(sm);           // alias over qs+ks

    const int bx = blockIdx.x;
    const int h  = bx & 7;
    const int nw = (bx >> 3) & 63;
    const int b  = bx >> 9;
    const size_t base = ((size_t)(b * NWIN + nw) * LL) * PROJ_ + h * HD;
    const int tid = threadIdx.x;
    const int w   = tid >> 5;
    const int lane = tid & 31;
    const int mkind = g_mask_kind;

    {
        const __half hz = __float2half_rn(0.0f);
        for (int idx = tid; idx < 15 * QLDH; idx += 256) {
            const int o = 49 * QLDH + idx;
            qs[o] = hz; ks_[o] = hz; vs[o] = hz;
        }
    }
    for (int idx = tid; idx < LL * 8; idx += 256) {
        const int r = idx >> 3;
        const int c = (idx & 7) << 2;
        const size_t g = base + (size_t)r * PROJ_ + c;
        *reinterpret_cast<uint2*>(&qs[r * QLDH + c])  = *reinterpret_cast<const uint2*>(&Q[g]);
        *reinterpret_cast<uint2*>(&ks_[r * QLDH + c]) = *reinterpret_cast<const uint2*>(&K[g]);
        *reinterpret_cast<uint2*>(&vs[r * QLDH + c])  = *reinterpret_cast<const uint2*>(&V[g]);
    }

    // Prefetch mask bits (rows w + 8*ri)
    unsigned int mbits = 0;
    {
        const size_t moff = (size_t)nw * LL * LL;
        const int c1ok = (lane + 32 < LL);
#pragma unroll
        for (int ri = 0; ri < 7; ri++) {
            const int r = w + 8 * ri;
            if (r < LL) {
                const size_t e0 = moff + (size_t)r * LL + lane;
                int m0, m1 = 0;
                if (mkind == 0) {
                    m0 = ((const int*)mask)[e0];
                    if (c1ok) m1 = ((const int*)mask)[e0 + 32];
                } else if (mkind == 1) {
                    m0 = ((const unsigned char*)mask)[e0];
                    if (c1ok) m1 = ((const unsigned char*)mask)[e0 + 32];
                } else {
                    m0 = (((const float*)mask)[e0] != 0.0f);
                    if (c1ok) m1 = (((const float*)mask)[e0 + 32] != 0.0f);
                }
                mbits |= (m0 ? 1u : 0u) << (2 * ri);
                mbits |= (m1 ? 1u : 0u) << (2 * ri + 1);
            }
        }
    }
    __syncthreads();

    // ---- S = Q @ K^T (64x64x32 fp16), 16 tiles, 2 per warp ----
    {
        wmma::fragment<wmma::matrix_a, 16, 16, 16, __half, wmma::row_major> fa;
        wmma::fragment<wmma::matrix_b, 16, 16, 16, __half, wmma::col_major> fb;
        wmma::fragment<wmma::accumulator, 16, 16, 16, float> fc[2];
        wmma::fill_fragment(fc[0], 0.0f);
        wmma::fill_fragment(fc[1], 0.0f);

        const int ti = w >> 1;
        const int tj0 = (w & 1) * 2;

#pragma unroll
        for (int k = 0; k < 32; k += 16) {
            wmma::load_matrix_sync(fa, &qs[ti * 16 * QLDH + k], QLDH);
#pragma unroll
            for (int u = 0; u < 2; u++) {
                wmma::load_matrix_sync(fb, &ks_[(tj0 + u) * 16 * QLDH + k], QLDH);
                wmma::mma_sync(fc[u], fa, fb, fc[u]);
            }
        }
#pragma unroll
        for (int u = 0; u < 2; u++)
            wmma::store_matrix_sync(&ss[ti * 16 * SLDF + (tj0 + u) * 16], fc[u],
                                    SLDF, wmma::mem_row_major);
    }
    __syncthreads();   // qs/ks dead from here -> ph alias is safe

    // ---- Fused scale + mask + max-free softmax -> P (half) ----
    // Scores are O(1); masked = -1000 -> __expf underflows to exactly 0.
    // eps guards the (measure-zero) all-masked-row case against div-by-0.
    {
        const float scale = 0.17677669529663687f;
        const int c1ok = (lane + 32 < LL);
#pragma unroll
        for (int ri = 0; ri < 7; ri++) {
            const int r = w + 8 * ri;
            if (r < LL) {
                float v0 = ss[r * SLDF + lane] * scale;
                if ((mbits >> (2 * ri)) & 1u) v0 = -1000.0f;
                const float e0 = __expf(v0);
                float e1 = 0.0f;
                if (c1ok) {
                    float v1 = ss[r * SLDF + lane + 32] * scale;
                    if ((mbits >> (2 * ri + 1)) & 1u) v1 = -1000.0f;
                    e1 = __expf(v1);
                }
                float s = e0 + e1;
#pragma unroll
                for (int o = 16; o; o >>= 1) s += __shfl_xor_sync(0xffffffffu, s, o);
                const float inv = 1.0f / (s + 1e-30f);
                ph[r * PLDH + lane] = __float2half_rn(e0 * inv);
                ph[r * PLDH + 32 + lane] =
                    c1ok ? __float2half_rn(e1 * inv) : __float2half_rn(0.0f);
            }
        }
        // P pad rows 49..63: zero (V-side pad rows are zero; avoid garbage)
        for (int idx = tid; idx < 15 * PLDH / 2; idx += 256) {
            const int o = 49 * PLDH + idx * 2;
            *reinterpret_cast<__half2*>(&ph[o]) = __half2half2(__float2half_rn(0.0f));
        }
    }
    __syncthreads();

    // ---- Out = P @ V (64x32x64 fp16), 8 tiles, 1 per warp ----
    {
        wmma::fragment<wmma::matrix_a, 16, 16, 16, __half, wmma::row_major> pa;
        wmma::fragment<wmma::matrix_b, 16, 16, 16, __half, wmma::row_major> pb;
        wmma::fragment<wmma::accumulator, 16, 16, 16, float> fo;
        wmma::fill_fragment(fo, 0.0f);

        const int ti = w >> 1;
        const int tj = w & 1;

#pragma unroll
        for (int k = 0; k < 64; k += 16) {
            wmma::load_matrix_sync(pa, &ph[ti * 16 * PLDH + k], PLDH);
            wmma::load_matrix_sync(pb, &vs[k * QLDH + tj * 16], QLDH);
            wmma::mma_sync(fo, pa, pb, fo);
        }
        wmma::store_matrix_sync(&ss[ti * 16 * SLDF + tj * 16], fo, SLDF,
                                wmma::mem_row_major);
    }
    __syncthreads();

    // ---- Write valid 49x32 output as half ----
    for (int idx = tid; idx < LL * 8; idx += 256) {
        const int r = idx >> 3;
        const int c = (idx & 7) << 2;
        union { __half2 h[2]; uint2 u; } pk;
        pk.h[0] = __floats2half2_rn(ss[r * SLDF + c],     ss[r * SLDF + c + 1]);
        pk.h[1] = __floats2half2_rn(ss[r * SLDF + c + 2], ss[r * SLDF + c + 3]);
        *reinterpret_cast<uint2*>(&O[base + (size_t)r * PROJ_ + c]) = pk.u;
    }
}

// ---------------------------------------------------------------------------
extern "C" void kernel_launch(void* const* d_in, const int* in_sizes, int n_in,
                              void* d_out, int out_size)
{
    const float* query = (const float*)d_in[0];
    const float* key_  = (const float*)d_in[1];
    const float* value = (const float*)d_in[2];
    const void*  mask  = d_in[3];
    const float* Wq = (const float*)d_in[4];
    const float* bq = (const float*)d_in[5];
    const float* Wk = (const float*)d_in[6];
    const float* bk = (const float*)d_in[7];
    const float* Wv = (const float*)d_in[8];
    const float* Ww = (const float*)d_in[9];
    const float* bw = (const float*)d_in[10];

    __half *qp, *kp, *vp, *wh;
    cudaGetSymbolAddress((void**)&qp, g_Q);
    cudaGetSymbolAddress((void**)&kp, g_K);
    cudaGetSymbolAddress((void**)&vp, g_V);
    cudaGetSymbolAddress((void**)&wh, g_Wh);

    __half* Wwh = wh + 3 * DD * PROJ_;

    const int smemProj = 128 * 4 + (2 * 128 * ALDH + 2 * 32 * (128 + 8)) * 2; // ~38.4KB
    const int smemOut  = 16 * (64 + 4) * 4 + (2 * 128 * ALDH + 2 * 32 * (64 + 8)) * 2;
    cudaFuncSetAttribute(gemm_fp16_proj3,
                         cudaFuncAttributeMaxDynamicSharedMemorySize, smemProj);
    cudaFuncSetAttribute(gemm_fp16_out,
                         cudaFuncAttributeMaxDynamicSharedMemorySize, smemOut);

    detect_mask_kind<<<1, 32>>>((const unsigned int*)mask);

    const int nel = DD * PROJ_;  // 49152
    round_all4<<<(4 * nel + 255) / 256, 256>>>(Wq, Wk, Wv, Ww, wh, nel);

    dim3 gproj(PROJ_ / 128, MTOT / 128, 3);   // (2, 784, 3)
    gemm_fp16_proj3<<<gproj, 128, smemProj>>>(query, key_, value, wh, bq, bk,
                                              qp, kp, vp, PROJ_, DD);

    attn_fp16<<<BB * NWIN * HEADS, 256>>>(qp, kp, vp, mask, qp);

    dim3 gout(DD / 64, MTOT / 128);        // (3, 784)
    gemm_fp16_out<<<gout, 128, smemOut>>>(qp, Wwh, bw, (float*)d_out, DD, PROJ_);
}